// round 14
// baseline (speedup 1.0000x reference)
#include <cuda_runtime.h>
#include <cuda_fp16.h>
#include <math.h>
#include <cstdint>

constexpr int HD = 1024;
constexpr int NH = 8;
constexpr int DH = 128;
constexpr int BB = 4;
constexpr int TT = 2048;
constexpr int MM = BB * TT; // 8192

typedef unsigned long long ull;

// ---- scratch (allocation-free) ----
__device__ __half g_xn[MM * 1024];          // LN out fp16
__device__ __half g_w[4][1024 * 1024];      // weights fp16 (contiguous: q,k,v,o)
__device__ __half g_q[32 * TT * 128];       // [B*NH][T][128], pre-scaled
__device__ __half g_k[32 * TT * 128];
__device__ __half g_v[32 * TT * 128];
__device__ __half g_attn[MM * 1024];        // attn fp16 [B,T,1024]

// ============================================================
// helpers
// ============================================================
__device__ __forceinline__ uint32_t s2u(const void* p) {
    uint32_t a;
    asm("{ .reg .u64 t; cvta.to.shared.u64 t, %1; cvt.u32.u64 %0, t; }" : "=r"(a) : "l"(p));
    return a;
}
__device__ __forceinline__ void cpasync16(uint32_t smem, const void* g) {
    asm volatile("cp.async.cg.shared.global [%0], [%1], 16;" :: "r"(smem), "l"(g));
}
__device__ __forceinline__ void cpcommit() { asm volatile("cp.async.commit_group;" ::: "memory"); }
template<int N> __device__ __forceinline__ void cpwait() {
    asm volatile("cp.async.wait_group %0;" :: "n"(N) : "memory");
}
__device__ __forceinline__ void ldsm4(uint32_t* r, uint32_t addr) {
    asm volatile("ldmatrix.sync.aligned.m8n8.x4.shared.b16 {%0,%1,%2,%3}, [%4];"
                 : "=r"(r[0]), "=r"(r[1]), "=r"(r[2]), "=r"(r[3]) : "r"(addr));
}
__device__ __forceinline__ void ldsm4t(uint32_t* r, uint32_t addr) {
    asm volatile("ldmatrix.sync.aligned.m8n8.x4.trans.shared.b16 {%0,%1,%2,%3}, [%4];"
                 : "=r"(r[0]), "=r"(r[1]), "=r"(r[2]), "=r"(r[3]) : "r"(addr));
}
__device__ __forceinline__ void mma16816(float* d, const uint32_t* a, uint32_t b0, uint32_t b1) {
    asm volatile("mma.sync.aligned.m16n8k16.row.col.f32.f16.f16.f32 "
                 "{%0,%1,%2,%3}, {%4,%5,%6,%7}, {%8,%9}, {%0,%1,%2,%3};"
                 : "+f"(d[0]), "+f"(d[1]), "+f"(d[2]), "+f"(d[3])
                 : "r"(a[0]), "r"(a[1]), "r"(a[2]), "r"(a[3]), "r"(b0), "r"(b1));
}
__device__ __forceinline__ uint32_t pack_h2(float a, float b) {
    __half2 h = __floats2half2_rn(a, b);
    return *(uint32_t*)&h;
}

// ============================================================
// LayerNorm -> fp16 [row][1024]
// ============================================================
__global__ void __launch_bounds__(256) ln_kernel(
    const float* __restrict__ x, const float* __restrict__ gamma,
    const float* __restrict__ beta, __half* __restrict__ xn)
{
    int row = blockIdx.x;
    int tid = threadIdx.x;
    const float* xr = x + (size_t)row * HD;
    float4 v = *(const float4*)&xr[tid * 4];
    float s  = v.x + v.y + v.z + v.w;
    float ss = v.x * v.x + v.y * v.y + v.z * v.z + v.w * v.w;
    #pragma unroll
    for (int o = 16; o; o >>= 1) {
        s  += __shfl_xor_sync(0xffffffffu, s,  o);
        ss += __shfl_xor_sync(0xffffffffu, ss, o);
    }
    __shared__ float rs[8], rss[8];
    if ((tid & 31) == 0) { rs[tid >> 5] = s; rss[tid >> 5] = ss; }
    __syncthreads();
    s = 0.f; ss = 0.f;
    #pragma unroll
    for (int i = 0; i < 8; i++) { s += rs[i]; ss += rss[i]; }
    float mu  = s * (1.0f / HD);
    float inv = rsqrtf(ss * (1.0f / HD) - mu * mu + 1e-5f);
    float4 g  = *(const float4*)&gamma[tid * 4];
    float4 be = *(const float4*)&beta[tid * 4];
    uint32_t p0 = pack_h2((v.x - mu) * inv * g.x + be.x, (v.y - mu) * inv * g.y + be.y);
    uint32_t p1 = pack_h2((v.z - mu) * inv * g.z + be.z, (v.w - mu) * inv * g.w + be.w);
    ull pk = (ull)p0 | ((ull)p1 << 32);
    *(ull*)&xn[(size_t)row * 1024 + tid * 4] = pk;
}

// all four weights -> fp16 in one launch
__global__ void __launch_bounds__(256) conv_half4(
    const float* __restrict__ W0, const float* __restrict__ W1,
    const float* __restrict__ W2, const float* __restrict__ W3,
    __half* __restrict__ Wh)
{
    int sel = blockIdx.x >> 10;
    const float* src = (sel == 0) ? W0 : (sel == 1) ? W1 : (sel == 2) ? W2 : W3;
    int i = (blockIdx.x & 1023) * 256 + threadIdx.x;
    float4 v = ((const float4*)src)[i];
    ull pk = (ull)pack_h2(v.x, v.y) | ((ull)pack_h2(v.z, v.w) << 32);
    *(ull*)&Wh[((size_t)sel << 20) + (size_t)i * 4] = pk;
}

// ============================================================
// mma.sync fp16 GEMM (R13, unchanged): CTA 128x128, 8 warps,
// warp 32x64, K-chunk 32, 4-stage cp.async, frag double-buffer.
// ============================================================
constexpr int GPITCH = 80;
constexpr int MAT_STAGE = 128 * GPITCH;
constexpr int STAGE_BYTES = 2 * MAT_STAGE;   // 20480
constexpr int GSTG = 4;
constexpr int GEMM_SMEM = GSTG * STAGE_BYTES; // 81920
constexpr int NCHUNK = 32;

__device__ __forceinline__ void gemm_load_chunk(
    const __half* __restrict__ A2, const __half* __restrict__ B2,
    int m0, int n0, int c, uint32_t sbase, int tid)
{
    int s = c % GSTG;
    int kc = c * 32;
    uint32_t aSt = sbase + s * STAGE_BYTES;
    uint32_t bSt = aSt + MAT_STAGE;
    #pragma unroll
    for (int p = 0; p < 2; p++) {
        int e = tid + (p << 8);
        int r = e >> 2, cc = e & 3;
        cpasync16(aSt + r * GPITCH + cc * 16, A2 + (size_t)(m0 + r) * 1024 + kc + cc * 8);
        cpasync16(bSt + r * GPITCH + cc * 16, B2 + (size_t)(n0 + r) * 1024 + kc + cc * 8);
    }
    cpcommit();
}

__device__ __forceinline__ void load_frags(
    uint32_t a[2][4], uint32_t b[4][4], uint32_t aSt, uint32_t bSt,
    int k16, int wm, int wn, int lr, int lk)
{
    #pragma unroll
    for (int mt = 0; mt < 2; mt++)
        ldsm4(a[mt], aSt + (wm * 32 + mt * 16 + lr) * GPITCH + (k16 * 16 + lk) * 2);
    #pragma unroll
    for (int nt = 0; nt < 4; nt++)
        ldsm4(b[nt], bSt + (wn * 64 + nt * 16 + lr) * GPITCH + (k16 * 16 + lk) * 2);
}

__device__ __forceinline__ void mma_set(float d[2][8][4], uint32_t a[2][4], uint32_t b[4][4])
{
    #pragma unroll
    for (int mt = 0; mt < 2; mt++)
        #pragma unroll
        for (int n8 = 0; n8 < 8; n8++) {
            int nt = n8 >> 1, odd = n8 & 1;
            mma16816(d[mt][n8], a[mt], b[nt][odd], b[nt][odd + 2]);
        }
}

__device__ __forceinline__ void gemm_core(
    const __half* A2, const __half* B2,
    int m0, int n0, uint32_t sbase, int tid, int lane, int wm, int wn,
    float d[2][8][4])
{
    int lr = lane & 15;
    int lk = (lane >> 4) << 3;

    gemm_load_chunk(A2, B2, m0, n0, 0, sbase, tid);
    gemm_load_chunk(A2, B2, m0, n0, 1, sbase, tid);
    gemm_load_chunk(A2, B2, m0, n0, 2, sbase, tid);
    gemm_load_chunk(A2, B2, m0, n0, 3, sbase, tid);
    cpwait<2>();
    __syncthreads();

    uint32_t fa[2][2][4], fb[2][4][4];
    load_frags(fa[0], fb[0], sbase, sbase + MAT_STAGE, 0, wm, wn, lr, lk);

    for (int c = 0; c < NCHUNK; c++) {
        uint32_t aSt  = sbase + (c % GSTG) * STAGE_BYTES;
        uint32_t bSt  = aSt + MAT_STAGE;
        uint32_t aStN = sbase + ((c + 1) % GSTG) * STAGE_BYTES;
        uint32_t bStN = aStN + MAT_STAGE;

        load_frags(fa[1], fb[1], aSt, bSt, 1, wm, wn, lr, lk);
        mma_set(d, fa[0], fb[0]);
        if (c + 1 < NCHUNK)
            load_frags(fa[0], fb[0], aStN, bStN, 0, wm, wn, lr, lk);
        mma_set(d, fa[1], fb[1]);

        __syncthreads();
        if (c + 4 < NCHUNK) gemm_load_chunk(A2, B2, m0, n0, c + 4, sbase, tid);
        else cpcommit();
        cpwait<2>();
        __syncthreads();
    }
}

// Fused QKV: B = concat(Wq,Wk,Wv) 3072x1024; fp16 out [B,NH,T,128]
__global__ void __launch_bounds__(256, 2) gemm_mma_qkv(
    const __half* __restrict__ A2, const __half* __restrict__ Ball,
    __half* __restrict__ Qo, __half* __restrict__ Ko, __half* __restrict__ Vo,
    float qscale)
{
    extern __shared__ char sm[];
    uint32_t sbase = s2u(sm);
    int tid = threadIdx.x, lane = tid & 31, warp = tid >> 5;
    int wm = warp >> 1, wn = warp & 1;
    int m0 = blockIdx.y << 7, n0 = blockIdx.x << 7;
    int sel = n0 >> 10;
    __half* outp = (sel == 0) ? Qo : (sel == 1) ? Ko : Vo;
    float scale = (sel == 0) ? qscale : 1.0f;

    float d[2][8][4];
    #pragma unroll
    for (int i = 0; i < 2; i++)
        #pragma unroll
        for (int j = 0; j < 8; j++)
            #pragma unroll
            for (int q = 0; q < 4; q++) d[i][j][q] = 0.f;

    gemm_core(A2, Ball, m0, n0, sbase, tid, lane, wm, wn, d);

    int mb = m0 + wm * 32 + (lane >> 2);
    int nb = n0 + wn * 64 + (lane & 3) * 2;
    #pragma unroll
    for (int mt = 0; mt < 2; mt++) {
        #pragma unroll
        for (int n8 = 0; n8 < 8; n8++) {
            int n = nb + n8 * 8;
            #pragma unroll
            for (int half = 0; half < 2; half++) {
                int m = mb + mt * 16 + half * 8;
                float c0 = d[mt][n8][half * 2] * scale, c1 = d[mt][n8][half * 2 + 1] * scale;
                int bI = m >> 11, t = m & 2047;
                int h = (n >> 7) & 7, dd = n & 127;
                size_t base = ((size_t)(bI * NH + h) * TT + t) * 128 + dd;
                *(uint32_t*)&outp[base] = pack_h2(c0, c1);
            }
        }
    }
}

// Output-projection: fp32 + residual
__global__ void __launch_bounds__(256, 2) gemm_mma_out(
    const __half* __restrict__ A2, const __half* __restrict__ B2,
    float* __restrict__ C, const float* __restrict__ R)
{
    extern __shared__ char sm[];
    uint32_t sbase = s2u(sm);
    int tid = threadIdx.x, lane = tid & 31, warp = tid >> 5;
    int wm = warp >> 1, wn = warp & 1;
    int m0 = blockIdx.y << 7, n0 = blockIdx.x << 7;

    float d[2][8][4];
    #pragma unroll
    for (int i = 0; i < 2; i++)
        #pragma unroll
        for (int j = 0; j < 8; j++)
            #pragma unroll
            for (int q = 0; q < 4; q++) d[i][j][q] = 0.f;

    gemm_core(A2, B2, m0, n0, sbase, tid, lane, wm, wn, d);

    int mb = m0 + wm * 32 + (lane >> 2);
    int nb = n0 + wn * 64 + (lane & 3) * 2;
    #pragma unroll
    for (int mt = 0; mt < 2; mt++) {
        #pragma unroll
        for (int n8 = 0; n8 < 8; n8++) {
            int n = nb + n8 * 8;
            #pragma unroll
            for (int half = 0; half < 2; half++) {
                int m = mb + mt * 16 + half * 8;
                size_t idx = (size_t)m * HD + n;
                float2 rr = *(const float2*)&R[idx];
                *(float2*)&C[idx] = make_float2(d[mt][n8][half * 2] + rr.x,
                                                d[mt][n8][half * 2 + 1] + rr.y);
            }
        }
    }
}

// ============================================================
// Flash attention, S-lookahead: BM=64, BN=64, 4 warps, 128 thr,
// 2 CTAs/SM. Each iteration computes S(kb+1) FIRST (independent
// tensor stream), then softmax(kb) + PV(kb) — ptxas interleaves
// the S(kb+1) HMMAs with the softmax ALU/MUFU, filling the idle
// tensor window. Q fragments loaded by LDG (no Q smem). K double-
// buffered, V triple-buffered (V consumed one phase after K).
// ============================================================
constexpr int FPB = 272;                      // row pitch bytes
constexpr int KVSZ = 64 * FPB;                // 17408
constexpr int FL_K = 0;                       // 2 bufs
constexpr int FL_V = FL_K + 2 * KVSZ;         // 3 bufs
constexpr int FLASH_SMEM = FL_V + 3 * KVSZ;   // 87040 B

struct FlashCtx {
    uint32_t sb;
    const __half *kp, *vp;
    int tid, lane, w, g, tig, lr, lk, q0, qb;
};

__device__ __forceinline__ void fl_load_kv(const FlashCtx& c, int i) {
    uint32_t kD = c.sb + FL_K + (i & 1) * KVSZ;
    uint32_t vD = c.sb + FL_V + (i % 3) * KVSZ;
    int kn0 = i << 6;
    #pragma unroll
    for (int p = 0; p < 8; p++) {
        int e = c.tid + (p << 7);
        int r = e >> 4, cc = e & 15;
        cpasync16(kD + r * FPB + cc * 16, c.kp + (size_t)(kn0 + r) * 128 + cc * 8);
        cpasync16(vD + r * FPB + cc * 16, c.vp + (size_t)(kn0 + r) * 128 + cc * 8);
    }
    cpcommit();
}

__device__ __forceinline__ void fl_compute_S(
    const FlashCtx& c, float s[8][4], const uint32_t qf[8][4], int blk)
{
    uint32_t kB = c.sb + FL_K + (blk & 1) * KVSZ;
    #pragma unroll
    for (int i = 0; i < 8; i++)
        #pragma unroll
        for (int j = 0; j < 4; j++) s[i][j] = 0.f;
    #pragma unroll
    for (int k16 = 0; k16 < 8; k16++) {
        #pragma unroll
        for (int t = 0; t < 4; t++) {
            uint32_t b[4];
            ldsm4(b, kB + (t * 16 + c.lr) * FPB + (k16 * 16 + c.lk) * 2);
            mma16816(s[2 * t],     qf[k16], b[0], b[2]);
            mma16816(s[2 * t + 1], qf[k16], b[1], b[3]);
        }
    }
    if (blk == c.qb) {   // causal mask on the diagonal block
        int rg0 = c.q0 + c.w * 16 + c.g;
        int rg1 = rg0 + 8;
        int cgb = (blk << 6) + c.tig * 2;
        #pragma unroll
        for (int j = 0; j < 8; j++) {
            int cg = cgb + j * 8;
            if (cg     > rg0) s[j][0] = -1e30f;
            if (cg + 1 > rg0) s[j][1] = -1e30f;
            if (cg     > rg1) s[j][2] = -1e30f;
            if (cg + 1 > rg1) s[j][3] = -1e30f;
        }
    }
}

// One flash step: prefetch KV(kb+2), compute S(kb+1) into snx,
// softmax+PV on scu (block kb).
__device__ __forceinline__ void fl_step(
    const FlashCtx& c, int kb, float scu[8][4], float snx[8][4],
    const uint32_t qf[8][4], float o[16][4],
    float& m0r, float& m1r, float& l0r, float& l1r)
{
    __syncthreads();                       // retire reads of K(kb) / V(kb-1)
    if (kb + 2 <= c.qb) fl_load_kv(c, kb + 2); else cpcommit();
    cpwait<1>();
    __syncthreads();                       // KV(kb+1) globally visible

    if (kb + 1 <= c.qb)
        fl_compute_S(c, snx, qf, kb + 1);  // independent tensor stream

    // ---- softmax on scu (rows g, g+8) ----
    float mx0 = -1e30f, mx1 = -1e30f;
    #pragma unroll
    for (int j = 0; j < 8; j++) {
        mx0 = fmaxf(mx0, fmaxf(scu[j][0], scu[j][1]));
        mx1 = fmaxf(mx1, fmaxf(scu[j][2], scu[j][3]));
    }
    mx0 = fmaxf(mx0, __shfl_xor_sync(0xffffffffu, mx0, 1));
    mx0 = fmaxf(mx0, __shfl_xor_sync(0xffffffffu, mx0, 2));
    mx1 = fmaxf(mx1, __shfl_xor_sync(0xffffffffu, mx1, 1));
    mx1 = fmaxf(mx1, __shfl_xor_sync(0xffffffffu, mx1, 2));
    float mn0 = fmaxf(m0r, mx0), mn1 = fmaxf(m1r, mx1);
    float al0 = exp2f(m0r - mn0), al1 = exp2f(m1r - mn1);
    m0r = mn0; m1r = mn1;

    float ps0 = 0.f, ps1 = 0.f;
    #pragma unroll
    for (int j = 0; j < 8; j++) {
        scu[j][0] = exp2f(scu[j][0] - mn0);
        scu[j][1] = exp2f(scu[j][1] - mn0);
        scu[j][2] = exp2f(scu[j][2] - mn1);
        scu[j][3] = exp2f(scu[j][3] - mn1);
        ps0 += scu[j][0] + scu[j][1];
        ps1 += scu[j][2] + scu[j][3];
    }
    ps0 += __shfl_xor_sync(0xffffffffu, ps0, 1);
    ps0 += __shfl_xor_sync(0xffffffffu, ps0, 2);
    ps1 += __shfl_xor_sync(0xffffffffu, ps1, 1);
    ps1 += __shfl_xor_sync(0xffffffffu, ps1, 2);
    l0r = l0r * al0 + ps0;
    l1r = l1r * al1 + ps1;

    if (!__all_sync(0xffffffffu, (al0 == 1.f) & (al1 == 1.f))) {
        #pragma unroll
        for (int j = 0; j < 16; j++) {
            o[j][0] *= al0; o[j][1] *= al0;
            o[j][2] *= al1; o[j][3] *= al1;
        }
    }

    uint32_t pa[4][4];
    #pragma unroll
    for (int cc = 0; cc < 4; cc++) {
        pa[cc][0] = pack_h2(scu[2 * cc][0],     scu[2 * cc][1]);
        pa[cc][1] = pack_h2(scu[2 * cc][2],     scu[2 * cc][3]);
        pa[cc][2] = pack_h2(scu[2 * cc + 1][0], scu[2 * cc + 1][1]);
        pa[cc][3] = pack_h2(scu[2 * cc + 1][2], scu[2 * cc + 1][3]);
    }

    // ---- O += P V : V(kb) from the 3-slot ring ----
    uint32_t vB = c.sb + FL_V + (kb % 3) * KVSZ;
    #pragma unroll
    for (int cc = 0; cc < 4; cc++) {
        #pragma unroll
        for (int j = 0; j < 8; j++) {
            uint32_t bt[4];
            ldsm4t(bt, vB + (cc * 16 + c.lr) * FPB + (j * 16 + c.lk) * 2);
            mma16816(o[2 * j],     pa[cc], bt[0], bt[1]);
            mma16816(o[2 * j + 1], pa[cc], bt[2], bt[3]);
        }
    }
}

__global__ void __launch_bounds__(128, 2) flash_mma(
    const __half* __restrict__ Q2, const __half* __restrict__ K2,
    const __half* __restrict__ V2, __half* __restrict__ Aout)
{
    extern __shared__ char sm[];
    FlashCtx c;
    c.sb = s2u(sm);
    c.tid = threadIdx.x;
    int lane = c.tid & 31;
    c.lane = lane;
    c.w = c.tid >> 5;
    c.g = lane >> 2;
    c.tig = lane & 3;
    c.lr = lane & 15;
    c.lk = (lane >> 4) << 3;
    c.qb = gridDim.x - 1 - blockIdx.x;     // largest tiles first
    int bh = blockIdx.y;
    c.q0 = c.qb << 6;
    const __half* qp = Q2 + (size_t)bh * TT * 128;
    c.kp = K2 + (size_t)bh * TT * 128;
    c.vp = V2 + (size_t)bh * TT * 128;

    // KV(0), KV(1) in flight
    fl_load_kv(c, 0);
    if (c.qb >= 1) fl_load_kv(c, 1); else cpcommit();

    // Q fragments straight from gmem (ldmatrix A-frag layout)
    uint32_t qf[8][4];
    {
        const __half* q0p = qp + (size_t)(c.q0 + c.w * 16 + c.g) * 128 + c.tig * 2;
        #pragma unroll
        for (int c8 = 0; c8 < 8; c8++) {
            qf[c8][0] = *(const uint32_t*)(q0p + c8 * 16);
            qf[c8][1] = *(const uint32_t*)(q0p + 8 * 128 + c8 * 16);
            qf[c8][2] = *(const uint32_t*)(q0p + c8 * 16 + 8);
            qf[c8][3] = *(const uint32_t*)(q0p + 8 * 128 + c8 * 16 + 8);
        }
    }

    float o[16][4];
    #pragma unroll
    for (int i = 0; i < 16; i++)
        #pragma unroll
        for (int j = 0; j < 4; j++) o[i][j] = 0.f;
    float m0r = -1e30f, m1r = -1e30f, l0r = 0.f, l1r = 0.f;

    cpwait<1>();         // KV(0) done locally
    __syncthreads();     // KV(0) globally visible

    float s0[8][4], s1[8][4];
    fl_compute_S(c, s0, qf, 0);

    // even/odd unroll keeps s0/s1 as static registers
    for (int kb = 0; kb <= c.qb; kb += 2) {
        fl_step(c, kb, s0, s1, qf, o, m0r, m1r, l0r, l1r);
        if (kb + 1 <= c.qb)
            fl_step(c, kb + 1, s1, s0, qf, o, m0r, m1r, l0r, l1r);
    }

    // epilogue: normalize, fp16 store [B,T,1024]
    float inv0 = 1.f / l0r, inv1 = 1.f / l1r;
    int b = bh >> 3, h = bh & 7;
    int t0 = c.q0 + c.w * 16 + c.g;
    #pragma unroll
    for (int j = 0; j < 16; j++) {
        int d = j * 8 + c.tig * 2;
        size_t base0 = (size_t)(b * TT + t0) * 1024 + h * 128 + d;
        size_t base1 = base0 + 8 * 1024;
        *(uint32_t*)&Aout[base0] = pack_h2(o[j][0] * inv0, o[j][1] * inv0);
        *(uint32_t*)&Aout[base1] = pack_h2(o[j][2] * inv1, o[j][3] * inv1);
    }
}

// ============================================================
// Launch
// ============================================================
extern "C" void kernel_launch(void* const* d_in, const int* in_sizes, int n_in,
                              void* d_out, int out_size)
{
    const float* x     = (const float*)d_in[0];
    const float* gamma = (const float*)d_in[1];
    const float* beta  = (const float*)d_in[2];
    const float* Wq    = (const float*)d_in[3];
    const float* Wk    = (const float*)d_in[4];
    const float* Wv    = (const float*)d_in[5];
    const float* Wo    = (const float*)d_in[6];
    float* out = (float*)d_out;

    __half *xn, *w, *q, *k, *v, *attn;
    cudaGetSymbolAddress((void**)&xn,   g_xn);
    cudaGetSymbolAddress((void**)&w,    g_w);
    cudaGetSymbolAddress((void**)&q,    g_q);
    cudaGetSymbolAddress((void**)&k,    g_k);
    cudaGetSymbolAddress((void**)&v,    g_v);
    cudaGetSymbolAddress((void**)&attn, g_attn);

    cudaFuncSetAttribute(gemm_mma_qkv, cudaFuncAttributeMaxDynamicSharedMemorySize, GEMM_SMEM);
    cudaFuncSetAttribute(gemm_mma_out, cudaFuncAttributeMaxDynamicSharedMemorySize, GEMM_SMEM);
    cudaFuncSetAttribute(flash_mma, cudaFuncAttributeMaxDynamicSharedMemorySize, FLASH_SMEM);

    ln_kernel<<<MM, 256>>>(x, gamma, beta, xn);
    conv_half4<<<4096, 256>>>(Wq, Wk, Wv, Wo, w);

    // scale*log2(e) folded into Q so softmax runs in base 2
    const float qscale = 0.08838834764831845f * 1.44269504088896341f;
    gemm_mma_qkv<<<dim3(24, 64), 256, GEMM_SMEM>>>(xn, w, q, k, v, qscale);

    flash_mma<<<dim3(TT / 64, BB * NH), 128, FLASH_SMEM>>>(q, k, v, attn);

    gemm_mma_out<<<dim3(8, 64), 256, GEMM_SMEM>>>(attn, w + ((size_t)3 << 20), out, x);
}